// round 10
// baseline (speedup 1.0000x reference)
#include <cuda_runtime.h>
#include <math.h>

#define NROWS   65536
#define DIM     64
#define KC      512
#define NQ      (NROWS*DIM)
#define THREADS 1024
#define MTILE   64
#define NTILES  (NROWS/MTILE)    // 1024
#define GRID    148
#define XTS     68               // X^T row stride (floats, mult of 4)

// smem byte offsets
#define SMO_ET   0                        // E^T: 64 x 512 f32 = 131072 B
#define SMO_XT   131072                   // X^T: 64 x 68 f32  = 17408 B
#define SMO_SB   148480                   // 512 f32 code norms
#define SMO_SA   150528                   // 64 f32 row norms
#define SMO_KEYS 150784                   // 64 u64 argmin keys
#define SMEM_TOTAL 151296

// Output: [0] loss | [1..NQ] quantized_st (base out+1, 4B-aligned) |
//         [1+NQ] perplexity | [2+NQ..] indices (as float)

typedef unsigned long long ull;

__device__ float  g_ET[DIM*KC];     // E^T [d][k]
__device__ float  g_sb[KC];
__device__ int    g_hist[KC];
__device__ double g_sse;
__device__ unsigned g_done;

__device__ __forceinline__ ull splat2(float v) {
    ull r; asm("mov.b64 %0, {%1, %1};" : "=l"(r) : "f"(v)); return r;
}
__device__ __forceinline__ void upk2(ull v, float& lo, float& hi) {
    asm("mov.b64 {%0, %1}, %2;" : "=f"(lo), "=f"(hi) : "l"(v));
}
__device__ __forceinline__ ull fma2(ull a, ull b, ull c) {
    ull d; asm("fma.rn.f32x2 %0, %1, %2, %3;" : "=l"(d) : "l"(a), "l"(b), "l"(c));
    return d;
}
// order-preserving float -> u32 (total order) for (dd, k) min keys
__device__ __forceinline__ unsigned ord32(float f) {
    unsigned u = __float_as_uint(f);
    return (u & 0x80000000u) ? ~u : (u | 0x80000000u);
}

// ---- prep: E^T image + exact code norms + zero globals ----------------------
__global__ void prep_kernel(const float* __restrict__ emb) {
    int k = blockIdx.x * blockDim.x + threadIdx.x;
    if (k >= KC) return;
    if (k == 0) { g_sse = 0.0; g_done = 0u; }
    g_hist[k] = 0;

    const float* e = emb + (size_t)k * DIM;
    float b0 = 0.f, b1 = 0.f;
    #pragma unroll
    for (int i = 0; i < DIM; i += 2) {
        b0 = fmaf(e[i],     e[i],     b0);
        b1 = fmaf(e[i + 1], e[i + 1], b1);
    }
    g_sb[k] = b0 + b1;
    #pragma unroll
    for (int d = 0; d < DIM; d++)
        g_ET[d * KC + k] = e[d];
}

// -----------------------------------------------------------------------------
// Persistent GEMM-tiled VQ: 64-row x 512-code tiles, 1024 threads,
// 8 rows x 4 codes per thread (f32x2 row-pairs). Exact JAX argmin:
//   d_k = fl( fl(A + b_k) - 2*c_k ), first-index tie via (dd,k) min-key.
// -----------------------------------------------------------------------------
__global__ void __launch_bounds__(THREADS, 1)
vq_gemm_kernel(const float* __restrict__ inp,
               const float* __restrict__ emb,
               float* __restrict__ out)
{
    extern __shared__ char smc[];
    float* ET   = reinterpret_cast<float*>(smc + SMO_ET);
    float* XT   = reinterpret_cast<float*>(smc + SMO_XT);
    float* sbv  = reinterpret_cast<float*>(smc + SMO_SB);
    float* sA   = reinterpret_cast<float*>(smc + SMO_SA);
    ull*   keys = reinterpret_cast<ull*>(smc + SMO_KEYS);

    const int tid  = threadIdx.x;
    const int lane = tid & 31;
    const int rp   = tid >> 7;    // row-group 0..7 (8 rows)
    const int cg   = tid & 127;   // code-lane: codes cg + 128*j

    // one-time smem fill: E^T + code norms
    for (int i = tid; i < DIM * KC / 4; i += THREADS)
        reinterpret_cast<float4*>(ET)[i] =
            reinterpret_cast<const float4*>(g_ET)[i];
    for (int i = tid; i < KC; i += THREADS) sbv[i] = g_sb[i];

    for (int tile = blockIdx.x; tile < NTILES; tile += GRID) {
        __syncthreads();   // prior tile reads done (first iter: ET fill)

        // ---- prologue: 64 threads, one row each (validated exact A order) --
        if (tid < MTILE) {
            const float4* xp = reinterpret_cast<const float4*>(
                inp + (size_t)(tile * MTILE + tid) * DIM);
            float a0 = 0.f, a1 = 0.f;
            #pragma unroll
            for (int i = 0; i < 16; i++) {
                float4 v = xp[i];
                XT[(4 * i + 0) * XTS + tid] = v.x;
                XT[(4 * i + 1) * XTS + tid] = v.y;
                XT[(4 * i + 2) * XTS + tid] = v.z;
                XT[(4 * i + 3) * XTS + tid] = v.w;
                a0 = fmaf(v.x, v.x, a0);
                a1 = fmaf(v.y, v.y, a1);
                a0 = fmaf(v.z, v.z, a0);
                a1 = fmaf(v.w, v.w, a1);
            }
            sA[tid]   = a0 + a1;
            keys[tid] = ~0ull;
        }
        __syncthreads();

        // ---- mainloop: acc[i2][j], rows (rp*8+2i2,+1), code cg+128j --------
        ull acc[4][4];
        #pragma unroll
        for (int i2 = 0; i2 < 4; i2++)
            #pragma unroll
            for (int j = 0; j < 4; j++) acc[i2][j] = 0ull;

        const float* ETc = ET + cg;
        const float* XTr = XT + rp * 8;
        #pragma unroll 2
        for (int d = 0; d < DIM; d++) {
            ulonglong2 va = *reinterpret_cast<const ulonglong2*>(XTr + d * XTS);
            ulonglong2 vb = *reinterpret_cast<const ulonglong2*>(XTr + d * XTS + 4);
            const float* Ed = ETc + d * KC;
            ull s0 = splat2(Ed[0]);
            ull s1 = splat2(Ed[128]);
            ull s2 = splat2(Ed[256]);
            ull s3 = splat2(Ed[384]);
            acc[0][0] = fma2(va.x, s0, acc[0][0]);
            acc[1][0] = fma2(va.y, s0, acc[1][0]);
            acc[2][0] = fma2(vb.x, s0, acc[2][0]);
            acc[3][0] = fma2(vb.y, s0, acc[3][0]);
            acc[0][1] = fma2(va.x, s1, acc[0][1]);
            acc[1][1] = fma2(va.y, s1, acc[1][1]);
            acc[2][1] = fma2(vb.x, s1, acc[2][1]);
            acc[3][1] = fma2(vb.y, s1, acc[3][1]);
            acc[0][2] = fma2(va.x, s2, acc[0][2]);
            acc[1][2] = fma2(va.y, s2, acc[1][2]);
            acc[2][2] = fma2(vb.x, s2, acc[2][2]);
            acc[3][2] = fma2(vb.y, s2, acc[3][2]);
            acc[0][3] = fma2(va.x, s3, acc[0][3]);
            acc[1][3] = fma2(va.y, s3, acc[1][3]);
            acc[2][3] = fma2(vb.x, s3, acc[2][3]);
            acc[3][3] = fma2(vb.y, s3, acc[3][3]);
        }

        // ---- per-row local argmin keys over this thread's 4 codes ----------
        ull lkey[8];
        #pragma unroll
        for (int i = 0; i < 8; i++) lkey[i] = ~0ull;
        #pragma unroll
        for (int i2 = 0; i2 < 4; i2++) {
            float tA0 = sA[rp * 8 + 2 * i2];
            float tA1 = sA[rp * 8 + 2 * i2 + 1];
            #pragma unroll
            for (int j = 0; j < 4; j++) {
                int   k = cg + 128 * j;
                float b = sbv[k];
                float clo, chi;
                upk2(acc[i2][j], clo, chi);
                float t0  = tA0 + b;              // fl(A + b_k)
                float dd0 = t0 - 2.0f * clo;      // fl(t - 2c)
                ull  k0 = ((ull)ord32(dd0) << 32) | (unsigned)k;
                if (k0 < lkey[2 * i2]) lkey[2 * i2] = k0;
                float t1  = tA1 + b;
                float dd1 = t1 - 2.0f * chi;
                ull  k1 = ((ull)ord32(dd1) << 32) | (unsigned)k;
                if (k1 < lkey[2 * i2 + 1]) lkey[2 * i2 + 1] = k1;
            }
        }
        #pragma unroll
        for (int i = 0; i < 8; i++) {
            ull v = lkey[i];
            #pragma unroll
            for (int off = 16; off > 0; off >>= 1) {
                ull o = __shfl_xor_sync(0xFFFFFFFFu, v, off);
                v = (o < v) ? o : v;
            }
            if (lane == 0) atomicMin(&keys[rp * 8 + i], v);
        }
        __syncthreads();

        // ---- winners: 64 threads finish one row each (no reg arrays) -------
        if (tid < MTILE) {
            const int row = tile * MTILE + tid;
            const int bik = (int)(unsigned)(keys[tid] & 0xFFFFFFFFull);

            out[2 + NQ + row] = (float)bik;
            atomicAdd(&g_hist[bik], 1);

            const float4* xp = reinterpret_cast<const float4*>(
                inp + (size_t)row * DIM);
            const float4* ep = reinterpret_cast<const float4*>(
                emb + (size_t)bik * DIM);
            float* q = out + 1 + (size_t)row * DIM;  // 4B-aligned only

            float sse = 0.f;
            #pragma unroll
            for (int i = 0; i < 16; i++) {
                float4 xv = xp[i], ev = ep[i];
                float d0 = ev.x - xv.x, d1 = ev.y - xv.y;
                float d2 = ev.z - xv.z, d3 = ev.w - xv.w;
                q[4*i+0] = xv.x + d0;                // fl(x + fl(q-x))
                q[4*i+1] = xv.y + d1;
                q[4*i+2] = xv.z + d2;
                q[4*i+3] = xv.w + d3;
                sse += d0*d0 + d1*d1 + d2*d2 + d3*d3;
            }
            #pragma unroll
            for (int off = 16; off > 0; off >>= 1)
                sse += __shfl_xor_sync(0xFFFFFFFFu, sse, off);
            if (lane == 0) atomicAdd(&g_sse, (double)sse);
        }
    }

    // ---- last CTA finalizes loss & perplexity -------------------------------
    __threadfence();
    __syncthreads();
    __shared__ unsigned s_last;
    if (tid == 0)
        s_last = (atomicAdd(&g_done, 1u) == GRID - 1u) ? 1u : 0u;
    __syncthreads();
    if (s_last) {
        __threadfence();
        __shared__ float red[THREADS];
        float acc = 0.f;
        for (int b = tid; b < KC; b += THREADS) {
            float pb = (float)g_hist[b] * (1.0f / (float)NROWS);
            acc += pb * logf(pb + 1e-10f);
        }
        red[tid] = acc;
        __syncthreads();
        for (int off = THREADS / 2; off > 0; off >>= 1) {
            if (tid < off) red[tid] += red[tid + off];
            __syncthreads();
        }
        if (tid == 0) {
            out[0]      = (float)(1.25 * (g_sse * (1.0 / (double)NQ)));
            out[1 + NQ] = expf(-red[0]);
        }
    }
}

extern "C" void kernel_launch(void* const* d_in, const int* in_sizes, int n_in,
                              void* d_out, int out_size)
{
    const float* inp = (const float*)d_in[0];
    const float* emb = (const float*)d_in[1];
    if (n_in >= 2 && in_sizes[0] == KC * DIM) {
        const float* t = inp; inp = emb; emb = t;
    }
    float* out = (float*)d_out;

    cudaFuncSetAttribute(vq_gemm_kernel,
                         cudaFuncAttributeMaxDynamicSharedMemorySize,
                         SMEM_TOTAL);

    prep_kernel<<<4, 128>>>(emb);
    vq_gemm_kernel<<<GRID, THREADS, SMEM_TOTAL>>>(inp, emb, out);
}